// round 4
// baseline (speedup 1.0000x reference)
#include <cuda_runtime.h>
#include <math.h>

#define B   64
#define S   96
#define E   300
#define D   512
#define H   256
#define SEL 128
#define G5  1280   // 5*H
#define MLPD 1024
#define NC  3

// ---- static device scratch (no allocs allowed) ----
__device__ __align__(16) float g_states[B][S][D];     // 12.6 MB, L2-resident
__device__ float g_logits0[B][S - 1];
__device__ float g_hroot[B][H];

__device__ __forceinline__ double dsig(double x) { return 1.0 / (1.0 + exp(-x)); }

// Shared pair-logit piece: thread j's partial = tanh(preact_j) * Ws2[j].
// Used identically by initsel and the scan's phase 5 so cached and
// recomputed logits are bit-identical.
__device__ __forceinline__ float pair_logit_partial(
    const float* __restrict__ hL, const float* __restrict__ hR,
    const float* __restrict__ Ws1, const float* __restrict__ bs1,
    const float* __restrict__ Ws2, int j)
{
    float a[8];
#pragma unroll
    for (int m = 0; m < 8; m++) a[m] = 0.0f;
    const float* wp = Ws1 + j;
    for (int k = 0; k < 64; k++) {
#pragma unroll
        for (int m = 0; m < 4; m++)
            a[m] = __fmaf_rn(hL[m * 64 + k], wp[(m * 64 + k) * SEL], a[m]);
#pragma unroll
        for (int m = 0; m < 4; m++)
            a[4 + m] = __fmaf_rn(hR[m * 64 + k], wp[(256 + m * 64 + k) * SEL], a[4 + m]);
    }
    float s = __fadd_rn(__fadd_rn(__fadd_rn(a[0], a[1]), __fadd_rn(a[2], a[3])),
                        __fadd_rn(__fadd_rn(a[4], a[5]), __fadd_rn(a[6], a[7])));
    s = __fadd_rn(s, bs1[j]);
    double t = tanh((double)s);
    return (float)(t * (double)Ws2[j]);
}

// ======================================================================
// Kernel 1: encode  states[b][s][:] = embed[sent[b][s]] @ W_enc + b_enc
// ======================================================================
__global__ void encode_kernel(const int* __restrict__ sent,
                              const float* __restrict__ emb,
                              const float* __restrict__ Wenc,
                              const float* __restrict__ benc) {
    __shared__ float xs[8][E];
    __shared__ int tok[8];
    int row0 = blockIdx.x * 8;
    int tid = threadIdx.x;
    if (tid < 8) tok[tid] = sent[row0 + tid];
    __syncthreads();
    for (int i = tid; i < 8 * E; i += 128) {
        int r = i / E, k = i - r * E;
        xs[r][k] = emb[(long)tok[r] * E + k];
    }
    __syncthreads();
    int c = tid * 4;
    float4 acc[8];
#pragma unroll
    for (int r = 0; r < 8; r++) acc[r] = make_float4(0.f, 0.f, 0.f, 0.f);
    for (int k = 0; k < E; k++) {
        float4 w = *(const float4*)&Wenc[k * D + c];
#pragma unroll
        for (int r = 0; r < 8; r++) {
            float xv = xs[r][k];
            acc[r].x = __fmaf_rn(xv, w.x, acc[r].x);
            acc[r].y = __fmaf_rn(xv, w.y, acc[r].y);
            acc[r].z = __fmaf_rn(xv, w.z, acc[r].z);
            acc[r].w = __fmaf_rn(xv, w.w, acc[r].w);
        }
    }
    float4 bv = *(const float4*)&benc[c];
#pragma unroll
    for (int r = 0; r < 8; r++) {
        acc[r].x = __fadd_rn(acc[r].x, bv.x);
        acc[r].y = __fadd_rn(acc[r].y, bv.y);
        acc[r].z = __fadd_rn(acc[r].z, bv.z);
        acc[r].w = __fadd_rn(acc[r].w, bv.w);
        int gr = row0 + r;
        int b = gr / S, s = gr - b * S;
        *(float4*)&g_states[b][s][c] = acc[r];
    }
}

// ======================================================================
// Kernel 2: initial pair logits (95 per batch)
// grid (6 pair-groups, 64 batches), 128 threads (= SEL cols)
// ======================================================================
__global__ void initsel_kernel(const float* __restrict__ Ws1,
                               const float* __restrict__ bs1,
                               const float* __restrict__ Ws2,
                               const float* __restrict__ bs2) {
    __shared__ float hs[17][H];
    __shared__ float red[4];
    int b = blockIdx.y;
    int p0 = blockIdx.x * 16;
    int tid = threadIdx.x;
    int nrows = min(17, S - p0);
    for (int i = tid; i < nrows * H; i += 128) {
        int r = i >> 8, k = i & (H - 1);
        hs[r][k] = g_states[b][p0 + r][H + k];
    }
    __syncthreads();
    int npairs = min(16, (S - 1) - p0);
    for (int p = 0; p < npairs; p++) {
        float y = pair_logit_partial(hs[p], hs[p + 1], Ws1, bs1, Ws2, tid);
        for (int o = 16; o; o >>= 1)
            y = __fadd_rn(y, __shfl_xor_sync(0xffffffffu, y, o));
        if ((tid & 31) == 0) red[tid >> 5] = y;
        __syncthreads();
        if (tid == 0)
            g_logits0[b][p0 + p] =
                __fadd_rn(__fadd_rn(__fadd_rn(red[0], red[1]), __fadd_rn(red[2], red[3])), bs2[0]);
        __syncthreads();
    }
}

// ======================================================================
// Kernel 3: the 95-step scan. 32 CTAs, 2 batches per CTA, 640 threads.
// ======================================================================
#define BD 640
__global__ void __launch_bounds__(BD, 1)
scan_kernel(const float* __restrict__ Wc,  const float* __restrict__ bc,
            const float* __restrict__ Ws1, const float* __restrict__ bs1,
            const float* __restrict__ Ws2, const float* __restrict__ bs2) {
    __shared__ float xs[2][D];        // compose inputs
    __shared__ float xsel[4][D];      // staged sel inputs (2 batches x 2 pairs)
    __shared__ float as_[2][G5];      // raw gates
    __shared__ float lg[2][S];        // cached pair logits
    __shared__ int   pm[2][S];        // slot permutation
    __shared__ int   selidx[2];
    __shared__ int   sL[2], sR[2];
    __shared__ float red[4][4];
    __shared__ float amax[2][4];
    __shared__ int   amaxi[2][4];

    int tid = threadIdx.x;
    int cta = blockIdx.x;
    int gb0 = cta * 2;

    for (int i = tid; i < 2 * (S - 1); i += BD) {
        int b = i / (S - 1), j = i - b * (S - 1);
        lg[b][j] = g_logits0[gb0 + b][j];
    }
    for (int i = tid; i < 2 * S; i += BD) {
        int b = i / S, j = i - b * S;
        pm[b][j] = j;
    }
    __syncthreads();

    for (int t = 0; t < S - 1; t++) {
        int n = S - t;        // active items
        int np = n - 1;       // active pairs

        // ---- Phase 0: per-batch argmax (first occurrence on ties) ----
        if (tid < 256) {
            int b = tid >> 7, lt = tid & 127;
            float best = -1e30f; int bi = 0;
            for (int j = lt; j < np; j += 128) {
                float v = lg[b][j];
                if (v > best) { best = v; bi = j; }
            }
            for (int o = 16; o; o >>= 1) {
                float ov = __shfl_xor_sync(0xffffffffu, best, o);
                int   oi = __shfl_xor_sync(0xffffffffu, bi, o);
                if (ov > best || (ov == best && oi < bi)) { best = ov; bi = oi; }
            }
            if ((lt & 31) == 0) { amax[b][lt >> 5] = best; amaxi[b][lt >> 5] = bi; }
        }
        __syncthreads();
        if (tid < 2) {
            int b = tid;
            float best = amax[b][0]; int bi = amaxi[b][0];
            for (int w = 1; w < 4; w++) {
                float v = amax[b][w]; int i2 = amaxi[b][w];
                if (v > best || (v == best && i2 < bi)) { best = v; bi = i2; }
            }
            selidx[b] = bi;
            sL[b] = pm[b][bi];
            sR[b] = pm[b][bi + 1];
        }
        __syncthreads();

        // ---- Phase 1: stage x = [h(left), h(right)] for both batches ----
        for (int i = tid; i < 2 * D; i += BD) {
            int b = i >> 9, k = i & (D - 1);
            int slot = (k < H) ? sL[b] : sR[b];
            int col  = (k < H) ? (H + k) : k;
            xs[b][k] = g_states[gb0 + b][slot][col];
        }
        __syncthreads();

        // ---- Phase 2: compose GEMV, 2 cols/thread, 4-way split accumulators,
        //      weights shared across both batches ----
        {
            int c = tid * 2;
            float a0x[4], a0y[4], a1x[4], a1y[4];
#pragma unroll
            for (int m = 0; m < 4; m++) { a0x[m] = 0.f; a0y[m] = 0.f; a1x[m] = 0.f; a1y[m] = 0.f; }
            const float* wp = Wc + c;
            for (int k = 0; k < 128; k++) {
#pragma unroll
                for (int m = 0; m < 4; m++) {
                    int idx = m * 128 + k;
                    float2 w = *(const float2*)(wp + (size_t)idx * G5);
                    float x0 = xs[0][idx];
                    float x1 = xs[1][idx];
                    a0x[m] = __fmaf_rn(x0, w.x, a0x[m]);
                    a0y[m] = __fmaf_rn(x0, w.y, a0y[m]);
                    a1x[m] = __fmaf_rn(x1, w.x, a1x[m]);
                    a1y[m] = __fmaf_rn(x1, w.y, a1y[m]);
                }
            }
            float2 bv = *(const float2*)&bc[c];
            as_[0][c]     = __fadd_rn(__fadd_rn(__fadd_rn(a0x[0], a0x[1]), __fadd_rn(a0x[2], a0x[3])), bv.x);
            as_[0][c + 1] = __fadd_rn(__fadd_rn(__fadd_rn(a0y[0], a0y[1]), __fadd_rn(a0y[2], a0y[3])), bv.y);
            as_[1][c]     = __fadd_rn(__fadd_rn(__fadd_rn(a1x[0], a1x[1]), __fadd_rn(a1x[2], a1x[3])), bv.x);
            as_[1][c + 1] = __fadd_rn(__fadd_rn(__fadd_rn(a1y[0], a1y[1]), __fadd_rn(a1y[2], a1y[3])), bv.y);
        }
        __syncthreads();

        // ---- Phase 3: gates (double-precision transcendentals) ----
        if (tid < 512) {
            int b = tid >> 8, h = tid & (H - 1);
            int gb = gb0 + b;
            double gi = (double)as_[b][h];
            double fl = (double)as_[b][H + h];
            double fr = (double)as_[b][2 * H + h];
            double go = (double)as_[b][3 * H + h];
            double gc = (double)as_[b][4 * H + h];
            double cl = (double)g_states[gb][sL[b]][h];
            double cr = (double)g_states[gb][sR[b]][h];
            float ccf = (float)(dsig(fl) * cl + dsig(fr) * cr + dsig(gi) * tanh(gc));
            float hpf = (float)(dsig(go) * tanh((double)ccf));
            g_states[gb][sL[b]][h]     = ccf;
            g_states[gb][sL[b]][H + h] = hpf;
        }
        __syncthreads();

        // ---- Phase 3b: shift perm / logits (remove merged entry) ----
        // FIX (R3): ii must be tid-192 for the second half; `tid & 191` is NOT
        // mod 192 (192 isn't a power of two) and skipped ii in [64,128).
        {
            float rv = 0.0f; int havework = 0, kind = 0, wb = 0, wj = 0;
            if (tid < 384) {
                kind = (tid >= 192);
                int ii = kind ? (tid - 192) : tid;   // proper bijection [0,192)
                int b = (ii >= 96) ? 1 : 0;
                int j = ii - b * 96;
                int idx = selidx[b];
                if (!kind) {  // perm: new pm[j] = old pm[j+1] for idx+1..n-2
                    if (j >= idx + 1 && j <= n - 2) {
                        havework = 1; rv = __int_as_float(pm[b][j + 1]); wb = b; wj = j;
                    }
                } else {      // logits: new lg[j] = old lg[j+1] for idx+1..n-3
                    if (j >= idx + 1 && j <= n - 3) {
                        havework = 1; rv = lg[b][j + 1]; wb = b; wj = j;
                    }
                }
            }
            __syncthreads();
            if (havework) {
                if (!kind) pm[wb][wj] = __float_as_int(rv);
                else       lg[wb][wj] = rv;
            }
        }
        __syncthreads();

        // ---- Phase 4: stage sel inputs for the (up to) 2 new pairs per batch ----
        for (int i = tid; i < 4 * D; i += BD) {
            int pi = i >> 9, k = i & (D - 1);
            int b = pi >> 1, s = pi & 1;
            int q = selidx[b] - 1 + s;
            if (q >= 0 && q <= n - 3) {
                int slot = (k < H) ? pm[b][q] : pm[b][q + 1];
                int col  = (k < H) ? (H + k) : k;
                xsel[pi][k] = g_states[gb0 + b][slot][col];
            }
        }
        __syncthreads();

        // ---- Phase 5: new pair logits (4 pair-GEMVs, 128 cols each) ----
        if (tid < 512) {
            int pi = tid >> 7;
            int b = pi >> 1, s = pi & 1;
            int j = tid & 127;
            int q = selidx[b] - 1 + s;
            if (q >= 0 && q <= n - 3) {
                float y = pair_logit_partial(&xsel[pi][0], &xsel[pi][H], Ws1, bs1, Ws2, j);
                for (int o = 16; o; o >>= 1)
                    y = __fadd_rn(y, __shfl_xor_sync(0xffffffffu, y, o));
                if ((tid & 31) == 0) red[pi][(tid >> 5) & 3] = y;
            }
        }
        __syncthreads();
        if (tid < 4) {
            int b = tid >> 1, s = tid & 1;
            int q = selidx[b] - 1 + s;
            if (q >= 0 && q <= n - 3)
                lg[b][q] = __fadd_rn(
                    __fadd_rn(__fadd_rn(red[tid][0], red[tid][1]),
                              __fadd_rn(red[tid][2], red[tid][3])), bs2[0]);
        }
        __syncthreads();
    }

    // ---- root hidden ----
    for (int i = tid; i < 2 * H; i += BD) {
        int b = i >> 8, h = i & (H - 1);
        g_hroot[gb0 + b][h] = g_states[gb0 + b][pm[b][0]][H + h];
    }
}

// ======================================================================
// Kernel 4: final MLP 256 -> 1024 -> 1024 -> 3. grid B, 256 threads.
// ======================================================================
__global__ void mlp_kernel(const float* __restrict__ Wm1, const float* __restrict__ bm1,
                           const float* __restrict__ Wm2, const float* __restrict__ bm2,
                           const float* __restrict__ Wout, const float* __restrict__ bout,
                           float* __restrict__ out) {
    __shared__ float hsh[H];
    __shared__ float x1[MLPD];
    __shared__ float x2[MLPD];
    __shared__ float red[8][NC];
    int b = blockIdx.x;
    int tid = threadIdx.x;
    if (tid < H) hsh[tid] = g_hroot[b][tid];
    __syncthreads();
    {
        int c = tid * 4;
        float4 acc = *(const float4*)&bm1[c];
        for (int k = 0; k < H; k++) {
            float4 w = *(const float4*)&Wm1[k * MLPD + c];
            float xv = hsh[k];
            acc.x = __fmaf_rn(xv, w.x, acc.x); acc.y = __fmaf_rn(xv, w.y, acc.y);
            acc.z = __fmaf_rn(xv, w.z, acc.z); acc.w = __fmaf_rn(xv, w.w, acc.w);
        }
        x1[c]     = fmaxf(acc.x, 0.0f);
        x1[c + 1] = fmaxf(acc.y, 0.0f);
        x1[c + 2] = fmaxf(acc.z, 0.0f);
        x1[c + 3] = fmaxf(acc.w, 0.0f);
    }
    __syncthreads();
    {
        int c = tid * 4;
        float4 acc = *(const float4*)&bm2[c];
        for (int k = 0; k < MLPD; k++) {
            float4 w = *(const float4*)&Wm2[k * MLPD + c];
            float xv = x1[k];
            acc.x = __fmaf_rn(xv, w.x, acc.x); acc.y = __fmaf_rn(xv, w.y, acc.y);
            acc.z = __fmaf_rn(xv, w.z, acc.z); acc.w = __fmaf_rn(xv, w.w, acc.w);
        }
        x2[c]     = fmaxf(acc.x, 0.0f);
        x2[c + 1] = fmaxf(acc.y, 0.0f);
        x2[c + 2] = fmaxf(acc.z, 0.0f);
        x2[c + 3] = fmaxf(acc.w, 0.0f);
    }
    __syncthreads();
    {
        float p0 = 0.0f, p1 = 0.0f, p2 = 0.0f;
        for (int k = tid; k < MLPD; k += 256) {
            float xv = x2[k];
            p0 = __fmaf_rn(xv, Wout[k * NC + 0], p0);
            p1 = __fmaf_rn(xv, Wout[k * NC + 1], p1);
            p2 = __fmaf_rn(xv, Wout[k * NC + 2], p2);
        }
        for (int o = 16; o; o >>= 1) {
            p0 = __fadd_rn(p0, __shfl_xor_sync(0xffffffffu, p0, o));
            p1 = __fadd_rn(p1, __shfl_xor_sync(0xffffffffu, p1, o));
            p2 = __fadd_rn(p2, __shfl_xor_sync(0xffffffffu, p2, o));
        }
        int lane = tid & 31, wrp = tid >> 5;
        if (lane == 0) { red[wrp][0] = p0; red[wrp][1] = p1; red[wrp][2] = p2; }
        __syncthreads();
        if (tid < NC) {
            float s = bout[tid];
            for (int w = 0; w < 8; w++) s = __fadd_rn(s, red[w][tid]);
            out[b * NC + tid] = s;
        }
    }
}

// ======================================================================
extern "C" void kernel_launch(void* const* d_in, const int* in_sizes, int n_in,
                              void* d_out, int out_size) {
    const int*   sent = (const int*)d_in[0];
    // d_in[1] = transitions (unused by reference)
    const float* emb  = (const float*)d_in[2];
    const float* Wenc = (const float*)d_in[3];
    const float* benc = (const float*)d_in[4];
    const float* Wc   = (const float*)d_in[5];
    const float* bc   = (const float*)d_in[6];
    const float* Ws1  = (const float*)d_in[7];
    const float* bs1  = (const float*)d_in[8];
    const float* Ws2  = (const float*)d_in[9];
    const float* bs2  = (const float*)d_in[10];
    const float* Wm1  = (const float*)d_in[11];
    const float* bm1  = (const float*)d_in[12];
    const float* Wm2  = (const float*)d_in[13];
    const float* bm2  = (const float*)d_in[14];
    const float* Wout = (const float*)d_in[15];
    const float* bout = (const float*)d_in[16];

    encode_kernel<<<768, 128>>>(sent, emb, Wenc, benc);
    initsel_kernel<<<dim3(6, 64), 128>>>(Ws1, bs1, Ws2, bs2);
    scan_kernel<<<32, BD>>>(Wc, bc, Ws1, bs1, Ws2, bs2);
    mlp_kernel<<<B, 256>>>(Wm1, bm1, Wm2, bm2, Wout, bout, (float*)d_out);
}